// round 1
// baseline (speedup 1.0000x reference)
#include <cuda_runtime.h>
#include <math.h>

// ---------------------------------------------------------------------------
// KroneckerMoE, fp32 baseline.
//   K1: router logits L = X @ W^T            (tiled sgemm, fp32)
//   K2: per-token top-2 + softmax            (warp reduction)
//   K3: per-token Y = sum_k p_k * A_k X B_k^T, *scale + bias  (warp per token)
// Scratch lives in __device__ globals (no allocations anywhere).
// ---------------------------------------------------------------------------

#define ROUTER_K   1024
#define MAX_TOKENS 16384
#define MAX_E      256

__device__ float g_logits[(size_t)MAX_TOKENS * MAX_E];
__device__ int   g_topidx[MAX_TOKENS * 2];
__device__ float g_topp  [MAX_TOKENS * 2];

// ---------------- Kernel 1: router GEMM ----------------
// X: [M, K] row-major, W: [E, K] row-major, L = X @ W^T : [M, E]
#define BM 128
#define BN 128
#define BK 16
#define TM 8
#define TN 8
// threads = (BM/TM)*(BN/TN) = 16*16 = 256

__global__ __launch_bounds__(256)
void router_gemm_kernel(const float* __restrict__ X, const float* __restrict__ W,
                        int M, int E) {
    __shared__ float Xs[BK][BM];
    __shared__ float Ws[BK][BN];
    const int bm  = blockIdx.x * BM;
    const int bn  = blockIdx.y * BN;
    const int tid = threadIdx.x;
    const int tx  = tid % (BN / TN);   // 0..15 (column group)
    const int ty  = tid / (BN / TN);   // 0..15 (row group)

    float acc[TM][TN];
    #pragma unroll
    for (int i = 0; i < TM; i++)
        #pragma unroll
        for (int j = 0; j < TN; j++) acc[i][j] = 0.f;

    for (int k0 = 0; k0 < ROUTER_K; k0 += BK) {
        // X tile: 128 rows x 16 cols = 512 float4 -> 2 per thread (transposed store)
        #pragma unroll
        for (int l = 0; l < 2; l++) {
            int id = tid + l * 256;
            int r  = id >> 2;            // 0..127
            int c4 = (id & 3) << 2;      // 0,4,8,12
            float4 v = *(const float4*)(X + (size_t)(bm + r) * ROUTER_K + k0 + c4);
            Xs[c4 + 0][r] = v.x; Xs[c4 + 1][r] = v.y;
            Xs[c4 + 2][r] = v.z; Xs[c4 + 3][r] = v.w;
        }
        // W tile: 128 rows x 16 cols = 512 float4 -> 2 per thread (transposed store)
        #pragma unroll
        for (int l = 0; l < 2; l++) {
            int id = tid + l * 256;
            int r  = id >> 2;
            int c4 = (id & 3) << 2;
            float4 v = *(const float4*)(W + (size_t)(bn + r) * ROUTER_K + k0 + c4);
            Ws[c4 + 0][r] = v.x; Ws[c4 + 1][r] = v.y;
            Ws[c4 + 2][r] = v.z; Ws[c4 + 3][r] = v.w;
        }
        __syncthreads();
        #pragma unroll
        for (int kk = 0; kk < BK; kk++) {
            float rm[TM], rn[TN];
            #pragma unroll
            for (int i = 0; i < TM; i++) rm[i] = Xs[kk][ty * TM + i];
            #pragma unroll
            for (int j = 0; j < TN; j++) rn[j] = Ws[kk][tx * TN + j];
            #pragma unroll
            for (int i = 0; i < TM; i++)
                #pragma unroll
                for (int j = 0; j < TN; j++)
                    acc[i][j] += rm[i] * rn[j];
        }
        __syncthreads();
    }
    #pragma unroll
    for (int i = 0; i < TM; i++) {
        float* dst = g_logits + (size_t)(bm + ty * TM + i) * E + bn + tx * TN;
        *(float4*)(dst + 0) = make_float4(acc[i][0], acc[i][1], acc[i][2], acc[i][3]);
        *(float4*)(dst + 4) = make_float4(acc[i][4], acc[i][5], acc[i][6], acc[i][7]);
    }
}

// ---------------- Kernel 2: top-2 + softmax ----------------
__device__ __forceinline__ bool pair_better(float v, int i, float w, int j) {
    // "larger value wins; ties -> smaller index" (matches lax.top_k stability)
    return (v > w) || (v == w && i < j);
}

__global__ void topk_kernel(int M, int E) {
    const int gw   = (blockIdx.x * blockDim.x + threadIdx.x) >> 5;
    const int lane = threadIdx.x & 31;
    if (gw >= M) return;
    const float* row = g_logits + (size_t)gw * E;

    float v0 = -3.4e38f, v1 = -3.4e38f;
    int   i0 = 0x7fffffff, i1 = 0x7fffffff;
    for (int e = lane; e < E; e += 32) {
        float v = row[e];
        if (pair_better(v, e, v0, i0)) { v1 = v0; i1 = i0; v0 = v; i0 = e; }
        else if (pair_better(v, e, v1, i1)) { v1 = v; i1 = e; }
    }
    #pragma unroll
    for (int off = 16; off > 0; off >>= 1) {
        float ov0 = __shfl_xor_sync(0xffffffffu, v0, off);
        int   oi0 = __shfl_xor_sync(0xffffffffu, i0, off);
        float ov1 = __shfl_xor_sync(0xffffffffu, v1, off);
        int   oi1 = __shfl_xor_sync(0xffffffffu, i1, off);
        if (pair_better(ov0, oi0, v0, i0)) {
            if (pair_better(v0, i0, ov1, oi1)) { v1 = v0; i1 = i0; }
            else                               { v1 = ov1; i1 = oi1; }
            v0 = ov0; i0 = oi0;
        } else if (pair_better(ov0, oi0, v1, i1)) {
            v1 = ov0; i1 = oi0;
        }
    }
    if (lane == 0) {
        float t   = expf(v1 - v0);        // <= 1
        float inv = 1.f / (1.f + t);
        g_topidx[2 * gw]     = i0;
        g_topidx[2 * gw + 1] = i1;
        g_topp  [2 * gw]     = inv;       // prob of top-1
        g_topp  [2 * gw + 1] = t * inv;   // prob of top-2
    }
}

// ---------------- Kernel 3: expert bilinear + combine + scale/bias ----------------
// One warp per token. lane = output row o. X,B staged in smem; A row in regs.
#define TPB_TOK 4   // tokens (warps) per block -> 128 threads

__global__ __launch_bounds__(128)
void expert_kernel(const float* __restrict__ x,
                   const float* __restrict__ Ae,
                   const float* __restrict__ Be,
                   const float* __restrict__ scale,
                   const float* __restrict__ bias,
                   float* __restrict__ out, int M) {
    __shared__ float Xs[TPB_TOK][1056];   // x tile; reused (stride-33) as Y staging
    __shared__ float Bs[TPB_TOK][1024];
    const int wid  = threadIdx.x >> 5;
    const int lane = threadIdx.x & 31;
    const int n    = blockIdx.x * TPB_TOK + wid;
    if (n >= M) return;
    float* xs = Xs[wid];
    float* bs = Bs[wid];

    {   // cooperative, coalesced load of x row (1024 floats)
        const float4* xg = (const float4*)(x + (size_t)n * 1024);
        float4* xs4 = (float4*)xs;
        #pragma unroll
        for (int i = 0; i < 8; i++) xs4[i * 32 + lane] = xg[i * 32 + lane];
    }
    const int   e0 = g_topidx[2 * n], e1 = g_topidx[2 * n + 1];
    const float w0 = g_topp[2 * n],   w1 = g_topp[2 * n + 1];

    float yacc[32];
    #pragma unroll
    for (int p = 0; p < 32; p++) yacc[p] = 0.f;

    __syncwarp();
    #pragma unroll
    for (int kk = 0; kk < 2; kk++) {
        const int   e = kk ? e1 : e0;
        const float w = kk ? w1 : w0;
        {   // cooperative load of B[e] (row-major 32x32)
            const float4* bg = (const float4*)(Be + (size_t)e * 1024);
            float4* bs4 = (float4*)bs;
            #pragma unroll
            for (int i = 0; i < 8; i++) bs4[i * 32 + lane] = bg[i * 32 + lane];
        }
        float a[32];   // A[e][lane][:] — this lane's output row of A
        {
            const float4* ag = (const float4*)(Ae + (size_t)e * 1024 + lane * 32);
            #pragma unroll
            for (int i = 0; i < 8; i++) {
                float4 v = ag[i];
                a[4*i+0] = v.x; a[4*i+1] = v.y; a[4*i+2] = v.z; a[4*i+3] = v.w;
            }
        }
        __syncwarp();
        // stage 1: T[j] = sum_i a[i] * X[i][j]   (Xs reads are warp-broadcast)
        float T[32];
        #pragma unroll
        for (int j = 0; j < 32; j++) T[j] = 0.f;
        #pragma unroll
        for (int i = 0; i < 32; i++) {
            const float4* xr = (const float4*)(xs + i * 32);
            const float ai = a[i];
            #pragma unroll
            for (int j4 = 0; j4 < 8; j4++) {
                float4 v = xr[j4];
                T[4*j4+0] += ai * v.x;
                T[4*j4+1] += ai * v.y;
                T[4*j4+2] += ai * v.z;
                T[4*j4+3] += ai * v.w;
            }
        }
        #pragma unroll
        for (int j = 0; j < 32; j++) T[j] *= w;   // fold in gate prob
        // stage 2: yacc[p] += sum_j T[j] * B[p][j]
        #pragma unroll
        for (int p = 0; p < 32; p++) {
            const float4* br = (const float4*)(bs + p * 32);
            float s = yacc[p];
            #pragma unroll
            for (int j4 = 0; j4 < 8; j4++) {
                float4 v = br[j4];
                s += T[4*j4+0] * v.x;
                s += T[4*j4+1] * v.y;
                s += T[4*j4+2] * v.z;
                s += T[4*j4+3] * v.w;
            }
            yacc[p] = s;
        }
        __syncwarp();   // before next expert overwrites bs
    }
    // stage Y through smem (padded stride 33 -> conflict-free), write coalesced
    #pragma unroll
    for (int p = 0; p < 32; p++) xs[lane * 33 + p] = yacc[p];
    __syncwarp();
    const float sc = *scale;
    float* og = out + (size_t)n * 1024;
    #pragma unroll
    for (int i = 0; i < 32; i++) {
        int q = i * 32 + lane;                    // out[n][o=i][p=lane]
        og[q] = xs[i * 33 + lane] * sc + bias[q];
    }
}

// ---------------- launch ----------------
extern "C" void kernel_launch(void* const* d_in, const int* in_sizes, int n_in,
                              void* d_out, int out_size) {
    const float* x  = (const float*)d_in[0];   // [B,S,1024] fp32
    const float* rw = (const float*)d_in[1];   // [E,1024]
    const float* Ae = (const float*)d_in[2];   // [E,32,32]
    const float* Be = (const float*)d_in[3];   // [E,32,32]
    const float* sc = (const float*)d_in[4];   // [1]
    const float* bi = (const float*)d_in[5];   // [1024]
    float* out = (float*)d_out;

    const int M = in_sizes[0] / ROUTER_K;      // 16384 tokens
    const int E = in_sizes[1] / ROUTER_K;      // 256 experts

    dim3 g1(M / BM, E / BN);
    router_gemm_kernel<<<g1, 256>>>(x, rw, M, E);

    int warps_total = M;
    topk_kernel<<<(warps_total * 32 + 255) / 256, 256>>>(M, E);

    expert_kernel<<<(M + TPB_TOK - 1) / TPB_TOK, 128>>>(x, Ae, Be, sc, bi, out, M);
}

// round 2
// speedup vs baseline: 1.4150x; 1.4150x over previous
#include <cuda_runtime.h>
#include <math.h>

// ---------------------------------------------------------------------------
// KroneckerMoE v2:
//   K1: router logits via tf32 mma.sync (tensor cores), L = X @ W^T
//   K2: fused per-token: approx top-4 -> exact fp32 re-rank -> softmax ->
//       expert bilinear with packed f32x2 FFMA2 -> scale+bias
// ---------------------------------------------------------------------------

#define ROUTER_K   1024
#define MAX_TOKENS 16384
#define MAX_E      256

__device__ float g_logits[(size_t)MAX_TOKENS * MAX_E];

// ======================= Kernel 1: tf32 mma router =========================
// X: [M,K] row-major, W: [E,K] row-major, L = X @ W^T
#define R_BM 128
#define R_BN 64
#define R_BK 32

__device__ __forceinline__ void mma_tf32(float d[4], const unsigned a[4], const unsigned b[2]) {
    asm volatile(
        "mma.sync.aligned.m16n8k8.row.col.f32.tf32.tf32.f32 "
        "{%0,%1,%2,%3}, {%4,%5,%6,%7}, {%8,%9}, {%0,%1,%2,%3};\n"
        : "+f"(d[0]), "+f"(d[1]), "+f"(d[2]), "+f"(d[3])
        : "r"(a[0]), "r"(a[1]), "r"(a[2]), "r"(a[3]), "r"(b[0]), "r"(b[1]));
}

__global__ __launch_bounds__(256)
void router_mma_kernel(const float* __restrict__ X, const float* __restrict__ W,
                       int M, int E) {
    __shared__ float Xs[R_BM][36];   // pad 36: (36r+c)%32 = (4r+c)%32 -> conflict-free frags
    __shared__ float Ws[R_BN][36];
    const int bm   = blockIdx.x * R_BM;
    const int bn   = blockIdx.y * R_BN;
    const int tid  = threadIdx.x;
    const int wid  = tid >> 5;
    const int lane = tid & 31;
    const int wm   = wid & 3;        // 4 warps along M
    const int wn   = wid >> 2;       // 2 warps along N
    const int g    = lane >> 2;      // groupID
    const int t    = lane & 3;       // thread-in-group

    float d[2][4][4];
    #pragma unroll
    for (int mt = 0; mt < 2; mt++)
        #pragma unroll
        for (int nt = 0; nt < 4; nt++)
            #pragma unroll
            for (int r = 0; r < 4; r++) d[mt][nt][r] = 0.f;

    for (int k0 = 0; k0 < ROUTER_K; k0 += R_BK) {
        // X tile 128x32: 1024 float4, 4 per thread
        #pragma unroll
        for (int l = 0; l < 4; l++) {
            int id = tid + l * 256;
            int r  = id >> 3;
            int c  = (id & 7) << 2;
            float4 v = *(const float4*)(X + (size_t)(bm + r) * ROUTER_K + k0 + c);
            *(float4*)&Xs[r][c] = v;
        }
        // W tile 64x32: 512 float4, 2 per thread
        #pragma unroll
        for (int l = 0; l < 2; l++) {
            int id = tid + l * 256;
            int r  = id >> 3;
            int c  = (id & 7) << 2;
            float4 v = *(const float4*)(W + (size_t)(bn + r) * ROUTER_K + k0 + c);
            *(float4*)&Ws[r][c] = v;
        }
        __syncthreads();
        #pragma unroll
        for (int ks = 0; ks < 4; ks++) {
            const int kk = ks * 8;
            unsigned a[2][4];
            #pragma unroll
            for (int mt = 0; mt < 2; mt++) {
                const int rb = wm * 32 + mt * 16;
                a[mt][0] = __float_as_uint(Xs[rb + g    ][kk + t    ]);
                a[mt][1] = __float_as_uint(Xs[rb + g + 8][kk + t    ]);
                a[mt][2] = __float_as_uint(Xs[rb + g    ][kk + t + 4]);
                a[mt][3] = __float_as_uint(Xs[rb + g + 8][kk + t + 4]);
            }
            unsigned b[4][2];
            #pragma unroll
            for (int nt = 0; nt < 4; nt++) {
                const int cb = wn * 32 + nt * 8;
                b[nt][0] = __float_as_uint(Ws[cb + g][kk + t    ]);
                b[nt][1] = __float_as_uint(Ws[cb + g][kk + t + 4]);
            }
            #pragma unroll
            for (int mt = 0; mt < 2; mt++)
                #pragma unroll
                for (int nt = 0; nt < 4; nt++)
                    mma_tf32(d[mt][nt], a[mt], b[nt]);
        }
        __syncthreads();
    }
    // epilogue: c0,c1 at (g, 2t), c2,c3 at (g+8, 2t)
    #pragma unroll
    for (int mt = 0; mt < 2; mt++) {
        #pragma unroll
        for (int nt = 0; nt < 4; nt++) {
            const int row = bm + wm * 32 + mt * 16 + g;
            const int col = bn + wn * 32 + nt * 8 + 2 * t;
            *(float2*)(g_logits + (size_t)row * E + col)       = make_float2(d[mt][nt][0], d[mt][nt][1]);
            *(float2*)(g_logits + (size_t)(row + 8) * E + col) = make_float2(d[mt][nt][2], d[mt][nt][3]);
        }
    }
}

// ================= Kernel 2: fused rerank + expert (f32x2) =================
#define TPB_TOK 4

__device__ __forceinline__ bool pair_better(float v, int i, float w, int j) {
    return (v > w) || (v == w && i < j);
}
__device__ __forceinline__ unsigned long long pack2(float lo, float hi) {
    unsigned long long r;
    asm("mov.b64 %0, {%1, %2};" : "=l"(r) : "r"(__float_as_uint(lo)), "r"(__float_as_uint(hi)));
    return r;
}
__device__ __forceinline__ void unpack2(unsigned long long v, float& lo, float& hi) {
    unsigned a, b;
    asm("mov.b64 {%0, %1}, %2;" : "=r"(a), "=r"(b) : "l"(v));
    lo = __uint_as_float(a); hi = __uint_as_float(b);
}
__device__ __forceinline__ void ffma2(unsigned long long& d, unsigned long long a, unsigned long long b) {
    asm("fma.rn.f32x2 %0, %1, %2, %0;" : "+l"(d) : "l"(a), "l"(b));
}

__global__ __launch_bounds__(128)
void expert_fused_kernel(const float* __restrict__ x,
                         const float* __restrict__ RW,
                         const float* __restrict__ Ae,
                         const float* __restrict__ Be,
                         const float* __restrict__ scale,
                         const float* __restrict__ bias,
                         float* __restrict__ out, int M, int E) {
    __shared__ float XsAll[TPB_TOK][1056];        // x row; reused for output staging
    __shared__ float BtAll[TPB_TOK][32 * 36];     // B transposed [j][p], pad 36
    const int wid  = threadIdx.x >> 5;
    const int lane = threadIdx.x & 31;
    const int n    = blockIdx.x * TPB_TOK + wid;
    if (n >= M) return;
    float* xs = XsAll[wid];
    float* bt = BtAll[wid];

    // ---- load x row (coalesced) ----
    {
        const float4* xg = (const float4*)(x + (size_t)n * 1024);
        float4* xs4 = (float4*)xs;
        #pragma unroll
        for (int i = 0; i < 8; i++) xs4[i * 32 + lane] = xg[i * 32 + lane];
    }
    __syncwarp();

    // ---- approx top-4 from tf32 logits ----
    const int NJ = E >> 5;                 // 8 for E=256
    float lv[8];
    const float* lrow = g_logits + (size_t)n * E;
    #pragma unroll
    for (int j = 0; j < 8; j++) lv[j] = (j < NJ) ? lrow[lane + 32 * j] : -3.4e38f;

    int cand[4];
    #pragma unroll
    for (int it = 0; it < 4; it++) {
        float bv = -3.4e38f; int be = 0x7fffffff;
        #pragma unroll
        for (int j = 0; j < 8; j++) {
            int e = lane + 32 * j;
            if (j < NJ && pair_better(lv[j], e, bv, be)) { bv = lv[j]; be = e; }
        }
        #pragma unroll
        for (int off = 16; off > 0; off >>= 1) {
            float ov = __shfl_xor_sync(0xffffffffu, bv, off);
            int   oe = __shfl_xor_sync(0xffffffffu, be, off);
            if (pair_better(ov, oe, bv, be)) { bv = ov; be = oe; }
        }
        cand[it] = be;
        if ((be & 31) == lane) lv[be >> 5] = -3.4e38f;   // mask winner
    }

    // ---- exact fp32 dots for the 4 candidates ----
    float xv[32];
    #pragma unroll
    for (int j = 0; j < 32; j++) xv[j] = xs[lane + 32 * j];
    float s[4];
    #pragma unroll
    for (int c = 0; c < 4; c++) {
        const float* wr = RW + (size_t)cand[c] * 1024;
        float acc = 0.f;
        #pragma unroll
        for (int j = 0; j < 32; j++) acc += xv[j] * wr[lane + 32 * j];
        s[c] = acc;
    }
    #pragma unroll
    for (int off = 16; off > 0; off >>= 1) {
        #pragma unroll
        for (int c = 0; c < 4; c++) s[c] += __shfl_xor_sync(0xffffffffu, s[c], off);
    }

    // ---- exact top-2 of the 4 + softmax ----
    float v0 = s[0]; int c0 = 0;
    #pragma unroll
    for (int c = 1; c < 4; c++)
        if (pair_better(s[c], cand[c], v0, cand[c0])) { v0 = s[c]; c0 = c; }
    float v1 = -3.4e38f; int c1 = -1;
    #pragma unroll
    for (int c = 0; c < 4; c++)
        if (c != c0 && (c1 < 0 || pair_better(s[c], cand[c], v1, cand[c1]))) { v1 = s[c]; c1 = c; }
    const int e0 = cand[c0], e1 = cand[c1];
    const float tt = expf(v1 - v0);
    const float w0 = 1.f / (1.f + tt);
    const float w1 = tt * w0;

    // ---- expert bilinear with packed f32x2 ----
    unsigned long long y2[16];
    #pragma unroll
    for (int p = 0; p < 16; p++) y2[p] = 0ull;

    #pragma unroll
    for (int kk = 0; kk < 2; kk++) {
        const int   e = kk ? e1 : e0;
        const float w = kk ? w1 : w0;
        // B[e] -> smem transposed: bt[j*36 + p]
        {
            const float4* bg = (const float4*)(Be + (size_t)e * 1024);
            #pragma unroll
            for (int i = 0; i < 8; i++) {
                int idx = i * 32 + lane;         // float4 index
                int p   = idx >> 3;
                int j4  = idx & 7;
                float4 v = bg[idx];
                bt[(4 * j4 + 0) * 36 + p] = v.x;
                bt[(4 * j4 + 1) * 36 + p] = v.y;
                bt[(4 * j4 + 2) * 36 + p] = v.z;
                bt[(4 * j4 + 3) * 36 + p] = v.w;
            }
        }
        // A row for this lane, gate weight folded in
        float a[32];
        {
            const float4* ag = (const float4*)(Ae + (size_t)e * 1024 + lane * 32);
            #pragma unroll
            for (int i = 0; i < 8; i++) {
                float4 v = ag[i];
                a[4*i+0] = v.x * w; a[4*i+1] = v.y * w;
                a[4*i+2] = v.z * w; a[4*i+3] = v.w * w;
            }
        }
        __syncwarp();

        // stage 1: T[j] = sum_i a[i] * X[i][j]   (packed over j)
        unsigned long long T2[16];
        #pragma unroll
        for (int j = 0; j < 16; j++) T2[j] = 0ull;
        #pragma unroll
        for (int i = 0; i < 32; i++) {
            unsigned long long ai2 = pack2(a[i], a[i]);
            const ulonglong2* xr = (const ulonglong2*)(xs + i * 32);
            #pragma unroll
            for (int q = 0; q < 8; q++) {
                ulonglong2 xx = xr[q];
                ffma2(T2[2*q],   ai2, xx.x);
                ffma2(T2[2*q+1], ai2, xx.y);
            }
        }
        // stage 2: y[p] += sum_j T[j] * Bt[j][p]  (packed over p)
        #pragma unroll
        for (int j2 = 0; j2 < 16; j2++) {
            float t0, t1; unpack2(T2[j2], t0, t1);
            unsigned long long tb0 = pack2(t0, t0);
            unsigned long long tb1 = pack2(t1, t1);
            const ulonglong2* br0 = (const ulonglong2*)(bt + (2*j2)   * 36);
            const ulonglong2* br1 = (const ulonglong2*)(bt + (2*j2+1) * 36);
            #pragma unroll
            for (int q = 0; q < 8; q++) {
                ulonglong2 bb = br0[q];
                ffma2(y2[2*q],   tb0, bb.x);
                ffma2(y2[2*q+1], tb0, bb.y);
            }
            #pragma unroll
            for (int q = 0; q < 8; q++) {
                ulonglong2 bb = br1[q];
                ffma2(y2[2*q],   tb1, bb.x);
                ffma2(y2[2*q+1], tb1, bb.y);
            }
        }
        __syncwarp();   // before next expert overwrites bt
    }

    // ---- epilogue: stage through smem, coalesced write with scale+bias ----
    #pragma unroll
    for (int p2 = 0; p2 < 16; p2++) {
        float lo, hi; unpack2(y2[p2], lo, hi);
        xs[lane * 33 + 2 * p2]     = lo;
        xs[lane * 33 + 2 * p2 + 1] = hi;
    }
    __syncwarp();
    const float sc = *scale;
    float* og = out + (size_t)n * 1024;
    #pragma unroll
    for (int i = 0; i < 32; i++) {
        int q = i * 32 + lane;
        og[q] = xs[i * 33 + lane] * sc + bias[q];
    }
}

// ================================ launch ===================================
extern "C" void kernel_launch(void* const* d_in, const int* in_sizes, int n_in,
                              void* d_out, int out_size) {
    const float* x  = (const float*)d_in[0];
    const float* rw = (const float*)d_in[1];
    const float* Ae = (const float*)d_in[2];
    const float* Be = (const float*)d_in[3];
    const float* sc = (const float*)d_in[4];
    const float* bi = (const float*)d_in[5];
    float* out = (float*)d_out;

    const int M = in_sizes[0] / ROUTER_K;   // 16384
    const int E = in_sizes[1] / ROUTER_K;   // 256

    dim3 g1(M / R_BM, E / R_BN);
    router_mma_kernel<<<g1, 256>>>(x, rw, M, E);

    expert_fused_kernel<<<(M + TPB_TOK - 1) / TPB_TOK, 128>>>(
        x, rw, Ae, Be, sc, bi, out, M, E);
}